// round 10
// baseline (speedup 1.0000x reference)
#include <cuda_runtime.h>
#include <cuda_bf16.h>

// B=8, D=3, N=M=4096 fused chamfer + MSE.
// Persistent pipelined main kernel: 592 blocks (= 4/SM x 148), each sweeps
// ~7 tiles (b,dir,isplit,s). Per tile: i-points staged via cp.async double
// buffer, j-chunk prefetched to regs (t<16) and preprocessed (-2x, n2) into
// smem at the bottom of the previous compute phase. One barrier per tile.
// Inner math: d = n1_i + fma2-chain(n2_j - 2*dot), f32x2 lanes = j-pair.

#define NPTS    4096
#define SPLITS  64
#define JCHUNK  64
#define JPAIRS  32
#define ISPLITS 4
#define TPB     256
#define IPER    4            // tile = 1024 i x 64 j
#define NBLK    592          // 4 * 148
#define NTILE   4096         // 8*2*4*64

__device__ float g_partial[8 * 2 * SPLITS * NPTS];   // 16 MB scratch
__device__ float g_sums[16 * 4];

typedef unsigned long long u64;
typedef unsigned int u32;

__device__ __forceinline__ u64 pack2(float lo, float hi) {
    u64 r; asm("mov.b64 %0, {%1, %2};" : "=l"(r) : "f"(lo), "f"(hi)); return r;
}
__device__ __forceinline__ u64 fma2(u64 a, u64 b, u64 c) {
    u64 r; asm("fma.rn.f32x2 %0, %1, %2, %3;" : "=l"(r) : "l"(a), "l"(b), "l"(c)); return r;
}
__device__ __forceinline__ void unpack2(u64 v, float& lo, float& hi) {
    asm("mov.b64 {%0, %1}, %2;" : "=f"(lo), "=f"(hi) : "l"(v));
}
__device__ __forceinline__ void lds_v2u64(u64& a, u64& b, const void* p) {
    u64 g = __cvta_generic_to_shared(p);
    asm("ld.shared.v2.b64 {%0, %1}, [%2];" : "=l"(a), "=l"(b) : "l"(g));
}
__device__ __forceinline__ void cp16(void* smem, const void* gmem) {
    u32 s = (u32)__cvta_generic_to_shared(smem);
    asm volatile("cp.async.cg.shared.global [%0], [%1], 16;" :: "r"(s), "l"(gmem));
}
#define CP_COMMIT() asm volatile("cp.async.commit_group;" ::: "memory")
#define CP_WAIT0()  asm volatile("cp.async.wait_group 0;" ::: "memory")

__global__ __launch_bounds__(TPB, 4)
void chamfer_partial_kernel(const float* __restrict__ points,
                            const float* __restrict__ points_trans) {
    __shared__ __align__(16) float ism[2][3][TPB * IPER];   // 24 KB staging
    __shared__ __align__(16) float sjA[2][JPAIRS * 4];
    __shared__ __align__(16) float sjB[2][JPAIRS * 4];

    const int t = threadIdx.x;
    int tile = blockIdx.x;

    float4 jX, jY, jZ;   // t<16: raw j coords for the *next* tile

    auto ldg_j = [&](int tl) {
        if (t < 16) {
            int dir = (tl >> 8) & 1, b = tl >> 9;
            const float* p2b = (dir ? points : points_trans) + b * 3 * NPTS;
            int j = (tl & (SPLITS - 1)) * JCHUNK + 4 * t;
            jX = *(const float4*)&p2b[j];
            jY = *(const float4*)&p2b[NPTS + j];
            jZ = *(const float4*)&p2b[2 * NPTS + j];
        }
    };
    auto sts_j = [&](int buf) {
        if (t < 16) {
            float4* A = (float4*)&sjA[buf][8 * t];
            A[0] = make_float4(-2.f * jX.x, -2.f * jX.y, -2.f * jY.x, -2.f * jY.y);
            A[1] = make_float4(-2.f * jX.z, -2.f * jX.w, -2.f * jY.z, -2.f * jY.w);
            float4* Bv = (float4*)&sjB[buf][8 * t];
            Bv[0] = make_float4(-2.f * jZ.x, -2.f * jZ.y,
                                jX.x * jX.x + jY.x * jY.x + jZ.x * jZ.x,
                                jX.y * jX.y + jY.y * jY.y + jZ.y * jZ.y);
            Bv[1] = make_float4(-2.f * jZ.z, -2.f * jZ.w,
                                jX.z * jX.z + jY.z * jY.z + jZ.z * jZ.z,
                                jX.w * jX.w + jY.w * jY.w + jZ.w * jZ.w);
        }
    };
    auto cp_i = [&](int tl, int buf) {
        int dir = (tl >> 8) & 1, b = tl >> 9;
        const float* p1b = (dir ? points_trans : points) + b * 3 * NPTS;
        int ib = ((tl >> 6) & (ISPLITS - 1)) * (TPB * IPER) + 4 * t;
        cp16(&ism[buf][0][4 * t], &p1b[ib]);
        cp16(&ism[buf][1][4 * t], &p1b[NPTS + ib]);
        cp16(&ism[buf][2][4 * t], &p1b[2 * NPTS + ib]);
    };

    // ---- prime the pipeline for the first tile ----
    ldg_j(tile);
    cp_i(tile, 0);
    CP_COMMIT();
    CP_WAIT0();
    sts_j(0);
    __syncthreads();

    int cur = 0;
    for (;;) {
        const int nxt = tile + NBLK;
        const bool has_next = (nxt < NTILE);
        if (has_next) {
            ldg_j(nxt);                 // LDG -> regs (t<16); consumed at bottom
            cp_i(nxt, cur ^ 1);         // LDGSTS -> other i buffer
        }
        CP_COMMIT();

        // ---- compute phase on buffer `cur` ----
        float4 vx = *(const float4*)&ism[cur][0][4 * t];
        float4 vy = *(const float4*)&ism[cur][1][4 * t];
        float4 vz = *(const float4*)&ism[cur][2][4 * t];
        float xs[IPER] = {vx.x, vx.y, vx.z, vx.w};
        float ys[IPER] = {vy.x, vy.y, vy.z, vy.w};
        float zs[IPER] = {vz.x, vz.y, vz.z, vz.w};

        u64 Xb[IPER], Yb[IPER], Zb[IPER];
        float n1[IPER];
#pragma unroll
        for (int k = 0; k < IPER; ++k) {
            n1[k] = xs[k] * xs[k] + ys[k] * ys[k] + zs[k] * zs[k];
            Xb[k] = pack2(xs[k], xs[k]);
            Yb[k] = pack2(ys[k], ys[k]);
            Zb[k] = pack2(zs[k], zs[k]);
        }

        float mnlo[IPER], mnhi[IPER];
#pragma unroll
        for (int k = 0; k < IPER; ++k) { mnlo[k] = 3.0e38f; mnhi[k] = 3.0e38f; }

#pragma unroll 8
        for (int jp = 0; jp < JPAIRS; ++jp) {
            u64 xj, yj, zj, nj;
            lds_v2u64(xj, yj, &sjA[cur][4 * jp]);
            lds_v2u64(zj, nj, &sjB[cur][4 * jp]);
#pragma unroll
            for (int k = 0; k < IPER; ++k) {
                u64 d = fma2(Zb[k], zj, nj);
                d = fma2(Yb[k], yj, d);
                d = fma2(Xb[k], xj, d);
                float dlo, dhi;
                unpack2(d, dlo, dhi);
                mnlo[k] = fminf(mnlo[k], dlo);
                mnhi[k] = fminf(mnhi[k], dhi);
            }
        }

        {
            const int s      = tile & (SPLITS - 1);
            const int isplit = (tile >> 6) & (ISPLITS - 1);
            const int dir    = (tile >> 8) & 1;
            const int b      = tile >> 9;
            float* dst = g_partial + ((size_t)((b * 2 + dir) * SPLITS + s)) * NPTS;
            const int ib = isplit * (TPB * IPER) + 4 * t;
            float4 r;
            r.x = n1[0] + fminf(mnlo[0], mnhi[0]);
            r.y = n1[1] + fminf(mnlo[1], mnhi[1]);
            r.z = n1[2] + fminf(mnlo[2], mnhi[2]);
            r.w = n1[3] + fminf(mnlo[3], mnhi[3]);
            *(float4*)&dst[ib] = r;
        }

        if (has_next) sts_j(cur ^ 1);   // preprocess next j-chunk into other buf
        CP_WAIT0();
        __syncthreads();
        if (!has_next) break;
        tile = nxt;
        cur ^= 1;
    }
}

__global__ __launch_bounds__(TPB)
void chamfer_reduce_kernel() {
    const int bd = blockIdx.x >> 2;          // 0..15
    const int ic = blockIdx.x & 3;           // 0..3 (1024 i each)
    const int t  = threadIdx.x;

    const float* base = g_partial + (size_t)bd * SPLITS * NPTS;
    const int i = ic * 1024 + 4 * t;

    float4 m = make_float4(3.0e38f, 3.0e38f, 3.0e38f, 3.0e38f);
#pragma unroll 16
    for (int s2 = 0; s2 < SPLITS; ++s2) {
        float4 v = *(const float4*)&base[s2 * NPTS + i];
        m.x = fminf(m.x, v.x); m.y = fminf(m.y, v.y);
        m.z = fminf(m.z, v.z); m.w = fminf(m.w, v.w);
    }
    float sum = (m.x + m.y) + (m.z + m.w);

    __shared__ float red[TPB];
    red[t] = sum;
    __syncthreads();
    for (int off = TPB / 2; off >= 32; off >>= 1) {
        if (t < off) red[t] += red[t + off];
        __syncthreads();
    }
    if (t < 32) {
        float v = red[t];
#pragma unroll
        for (int off = 16; off > 0; off >>= 1)
            v += __shfl_xor_sync(0xFFFFFFFFu, v, off);
        if (t == 0) g_sums[bd * 4 + ic] = v;
    }
}

__global__ void mse_kernel(const float* __restrict__ pred, float* __restrict__ out) {
    int t = threadIdx.x;
    float v = 0.0f;
    if (t < 16) {
        float s = 0.0f;
#pragma unroll
        for (int c = 0; c < 4; ++c) s += g_sums[t * 4 + c];
        float cham = s * (1.0f / (float)NPTS);
        float d = pred[t] - cham;
        v = d * d;
    }
#pragma unroll
    for (int off = 16; off > 0; off >>= 1)
        v += __shfl_xor_sync(0xFFFFFFFFu, v, off);
    if (t == 0) out[0] = v * (1.0f / 16.0f);
}

extern "C" void kernel_launch(void* const* d_in, const int* in_sizes, int n_in,
                              void* d_out, int out_size) {
    const float* pred         = (const float*)d_in[0];   // [8,2]
    const float* points       = (const float*)d_in[1];   // [8,3,4096]
    const float* points_trans = (const float*)d_in[2];   // [8,3,4096]
    float* out = (float*)d_out;

    chamfer_partial_kernel<<<NBLK, TPB>>>(points, points_trans);
    chamfer_reduce_kernel<<<64, TPB>>>();
    mse_kernel<<<1, 32>>>(pred, out);
}

// round 11
// speedup vs baseline: 1.0217x; 1.0217x over previous
#include <cuda_runtime.h>
#include <cuda_bf16.h>

// B=8, D=3, N=M=4096 fused chamfer + MSE.
// d_ij = n1_i + (n2_j - 2*dot): 3-FMA2 chain, j coords premultiplied by -2,
// chain seeded with n2. f32x2 lanes carry a j-PAIR. float4 GMEM everywhere.
// R11: launch_bounds(256,3) -> 84-reg budget so ptxas keeps 4+ d-chains in
// flight (R9/R10 showed a 64-reg clamp serialized the chains -> issue 64%).
// Kernel 1: 4096 blocks = b(8) x dir(2) x isplit(4) x jsplit(64), 256 thr.
// Kernel 2: 64 blocks, float4 min over 64 j-chunks + partial sums.
// Kernel 3: 1 warp: means + MSE.

#define NPTS    4096
#define SPLITS  64           // j-splits
#define JCHUNK  64           // NPTS / SPLITS
#define JPAIRS  (JCHUNK / 2) // 32
#define ISPLITS 4
#define TPB     256
#define IPER    4            // ISPLITS*TPB*IPER = 4096 = NPTS (exact cover)

__device__ float g_partial[8 * 2 * SPLITS * NPTS];   // 16 MB scratch (L2-resident)
__device__ float g_sums[16 * 4];

typedef unsigned long long u64;

__device__ __forceinline__ u64 pack2(float lo, float hi) {
    u64 r; asm("mov.b64 %0, {%1, %2};" : "=l"(r) : "f"(lo), "f"(hi)); return r;
}
__device__ __forceinline__ u64 fma2(u64 a, u64 b, u64 c) {
    u64 r; asm("fma.rn.f32x2 %0, %1, %2, %3;" : "=l"(r) : "l"(a), "l"(b), "l"(c)); return r;
}
__device__ __forceinline__ void unpack2(u64 v, float& lo, float& hi) {
    asm("mov.b64 {%0, %1}, %2;" : "=f"(lo), "=f"(hi) : "l"(v));
}
__device__ __forceinline__ void lds_v2u64(u64& a, u64& b, const void* p) {
    u64 g = __cvta_generic_to_shared(p);
    asm("ld.shared.v2.b64 {%0, %1}, [%2];" : "=l"(a), "=l"(b) : "l"(g));
}

__global__ __launch_bounds__(TPB, 3)
void chamfer_partial_kernel(const float* __restrict__ points,
                            const float* __restrict__ points_trans) {
    const int blk    = blockIdx.x;              // 0..4095
    const int s      = blk & (SPLITS - 1);      // bits [0,6)
    const int isplit = (blk >> 6) & (ISPLITS - 1);
    const int dir    = (blk >> 8) & 1;
    const int b      = blk >> 9;

    const float* p1b = (dir ? points_trans : points) + b * 3 * NPTS;
    const float* p2b = (dir ? points : points_trans) + b * 3 * NPTS;

    // smem per j-pair: A = {-2x0,-2x1,-2y0,-2y1}, B = {-2z0,-2z1, n0, n1}
    __shared__ __align__(16) float sjA[JPAIRS * 4];
    __shared__ __align__(16) float sjB[JPAIRS * 4];

    const int t = threadIdx.x;

    if (t < 16) {                               // 16 thr x 4 j = 64 = JCHUNK
        int j = s * JCHUNK + 4 * t;
        float4 X = *(const float4*)&p2b[j];
        float4 Y = *(const float4*)&p2b[NPTS + j];
        float4 Z = *(const float4*)&p2b[2 * NPTS + j];
        float4* A = (float4*)&sjA[8 * t];
        A[0] = make_float4(-2.f * X.x, -2.f * X.y, -2.f * Y.x, -2.f * Y.y);
        A[1] = make_float4(-2.f * X.z, -2.f * X.w, -2.f * Y.z, -2.f * Y.w);
        float4* Bv = (float4*)&sjB[8 * t];
        Bv[0] = make_float4(-2.f * Z.x, -2.f * Z.y,
                            X.x * X.x + Y.x * Y.x + Z.x * Z.x,
                            X.y * X.y + Y.y * Y.y + Z.y * Z.y);
        Bv[1] = make_float4(-2.f * Z.z, -2.f * Z.w,
                            X.z * X.z + Y.z * Y.z + Z.z * Z.z,
                            X.w * X.w + Y.w * Y.w + Z.w * Z.w);
    }

    // Thread's 4 consecutive i points via 3 x LDG.128 (low MLP_p1).
    const int ib = isplit * (TPB * IPER) + 4 * t;   // < 4096 always
    float4 vx = *(const float4*)&p1b[ib];
    float4 vy = *(const float4*)&p1b[NPTS + ib];
    float4 vz = *(const float4*)&p1b[2 * NPTS + ib];

    float xs[IPER] = {vx.x, vx.y, vx.z, vx.w};
    float ys[IPER] = {vy.x, vy.y, vy.z, vy.w};
    float zs[IPER] = {vz.x, vz.y, vz.z, vz.w};

    u64 Xb[IPER], Yb[IPER], Zb[IPER];
    float n1[IPER];
#pragma unroll
    for (int k = 0; k < IPER; ++k) {
        n1[k] = xs[k] * xs[k] + ys[k] * ys[k] + zs[k] * zs[k];
        Xb[k] = pack2(xs[k], xs[k]);
        Yb[k] = pack2(ys[k], ys[k]);
        Zb[k] = pack2(zs[k], zs[k]);
    }

    float mnlo[IPER], mnhi[IPER];
#pragma unroll
    for (int k = 0; k < IPER; ++k) { mnlo[k] = 3.0e38f; mnhi[k] = 3.0e38f; }

    __syncthreads();

#pragma unroll 8
    for (int jp = 0; jp < JPAIRS; ++jp) {
        u64 xj, yj, zj, nj;
        lds_v2u64(xj, yj, &sjA[4 * jp]);   // (-2x0,-2x1), (-2y0,-2y1)
        lds_v2u64(zj, nj, &sjB[4 * jp]);   // (-2z0,-2z1), (n0,n1)
        u64 d0 = fma2(Zb[0], zj, nj);
        u64 d1 = fma2(Zb[1], zj, nj);
        u64 d2 = fma2(Zb[2], zj, nj);
        u64 d3 = fma2(Zb[3], zj, nj);
        d0 = fma2(Yb[0], yj, d0);
        d1 = fma2(Yb[1], yj, d1);
        d2 = fma2(Yb[2], yj, d2);
        d3 = fma2(Yb[3], yj, d3);
        d0 = fma2(Xb[0], xj, d0);
        d1 = fma2(Xb[1], xj, d1);
        d2 = fma2(Xb[2], xj, d2);
        d3 = fma2(Xb[3], xj, d3);
        float lo, hi;
        unpack2(d0, lo, hi);
        mnlo[0] = fminf(mnlo[0], lo); mnhi[0] = fminf(mnhi[0], hi);
        unpack2(d1, lo, hi);
        mnlo[1] = fminf(mnlo[1], lo); mnhi[1] = fminf(mnhi[1], hi);
        unpack2(d2, lo, hi);
        mnlo[2] = fminf(mnlo[2], lo); mnhi[2] = fminf(mnhi[2], hi);
        unpack2(d3, lo, hi);
        mnlo[3] = fminf(mnlo[3], lo); mnhi[3] = fminf(mnhi[3], hi);
    }

    float* dst = g_partial + ((size_t)((b * 2 + dir) * SPLITS + s)) * NPTS;
    float4 r;
    r.x = n1[0] + fminf(mnlo[0], mnhi[0]);
    r.y = n1[1] + fminf(mnlo[1], mnhi[1]);
    r.z = n1[2] + fminf(mnlo[2], mnhi[2]);
    r.w = n1[3] + fminf(mnlo[3], mnhi[3]);
    *(float4*)&dst[ib] = r;                 // STG.128
}

__global__ __launch_bounds__(TPB)
void chamfer_reduce_kernel() {
    const int bd = blockIdx.x >> 2;          // 0..15
    const int ic = blockIdx.x & 3;           // 0..3 (1024 i each)
    const int t  = threadIdx.x;

    const float* base = g_partial + (size_t)bd * SPLITS * NPTS;
    const int i = ic * 1024 + 4 * t;

    float4 m = make_float4(3.0e38f, 3.0e38f, 3.0e38f, 3.0e38f);
#pragma unroll 16
    for (int s2 = 0; s2 < SPLITS; ++s2) {
        float4 v = *(const float4*)&base[s2 * NPTS + i];
        m.x = fminf(m.x, v.x); m.y = fminf(m.y, v.y);
        m.z = fminf(m.z, v.z); m.w = fminf(m.w, v.w);
    }
    float sum = (m.x + m.y) + (m.z + m.w);

    __shared__ float red[TPB];
    red[t] = sum;
    __syncthreads();
    for (int off = TPB / 2; off >= 32; off >>= 1) {
        if (t < off) red[t] += red[t + off];
        __syncthreads();
    }
    if (t < 32) {
        float v = red[t];
#pragma unroll
        for (int off = 16; off > 0; off >>= 1)
            v += __shfl_xor_sync(0xFFFFFFFFu, v, off);
        if (t == 0) g_sums[bd * 4 + ic] = v;
    }
}

__global__ void mse_kernel(const float* __restrict__ pred, float* __restrict__ out) {
    int t = threadIdx.x;
    float v = 0.0f;
    if (t < 16) {
        float s = 0.0f;
#pragma unroll
        for (int c = 0; c < 4; ++c) s += g_sums[t * 4 + c];
        float cham = s * (1.0f / (float)NPTS);
        float d = pred[t] - cham;
        v = d * d;
    }
#pragma unroll
    for (int off = 16; off > 0; off >>= 1)
        v += __shfl_xor_sync(0xFFFFFFFFu, v, off);
    if (t == 0) out[0] = v * (1.0f / 16.0f);
}

extern "C" void kernel_launch(void* const* d_in, const int* in_sizes, int n_in,
                              void* d_out, int out_size) {
    const float* pred         = (const float*)d_in[0];   // [8,2]
    const float* points       = (const float*)d_in[1];   // [8,3,4096]
    const float* points_trans = (const float*)d_in[2];   // [8,3,4096]
    float* out = (float*)d_out;

    chamfer_partial_kernel<<<8 * 2 * ISPLITS * SPLITS, TPB>>>(points, points_trans);
    chamfer_reduce_kernel<<<64, TPB>>>();
    mse_kernel<<<1, 32>>>(pred, out);
}

// round 13
// speedup vs baseline: 1.0884x; 1.0653x over previous
#include <cuda_runtime.h>
#include <cuda_bf16.h>

// B=8, D=3, N=M=4096 fused chamfer + MSE — SHARED distance matrix.
// d(i,j) = |points_i - points_trans_j|^2 serves BOTH chamfer directions:
// d1 = row-min, d2 = col-min of the same matrix -> half the FMA work.
// d = fma2-chain( (n1_i + n2_j) - 2*dot ), f32x2 lanes carry a j-pair.
// Col-min: thread t handles jp=(t+iter)&31; each (warp,jp) smem slot has one
// writer per iteration; accumulate via read-min-write. __syncwarp() per
// iteration orders the cross-lane RAW (writer of iter k-1 != reader of k).
// Kernel 1: 2048 blocks = b(8) x isplit(4) x jsplit(64), 256 thr, IPER=4.
// Kernel 2: 40 blocks: rows (32) + cols (8) reduction.
// Kernel 3: 1 warp: means + MSE.

#define NPTS    4096
#define SPLITS  64
#define JCHUNK  64
#define JPAIRS  32
#define ISPLITS 4
#define TPB     256
#define IPER    4            // ISPLITS*TPB*IPER = 4096 = NPTS (exact cover)

__device__ float g_row[8 * SPLITS * NPTS];     // 8 MB: per-(b,s) row partial mins
__device__ float g_col[8 * ISPLITS * NPTS];    // 512 KB: per-(b,isplit) col partial mins
__device__ float g_sums[8 * 4];                // row partial sums
__device__ float g_colsum[8];                  // col sums

typedef unsigned long long u64;

__device__ __forceinline__ u64 pack2(float lo, float hi) {
    u64 r; asm("mov.b64 %0, {%1, %2};" : "=l"(r) : "f"(lo), "f"(hi)); return r;
}
__device__ __forceinline__ u64 fma2(u64 a, u64 b, u64 c) {
    u64 r; asm("fma.rn.f32x2 %0, %1, %2, %3;" : "=l"(r) : "l"(a), "l"(b), "l"(c)); return r;
}
__device__ __forceinline__ u64 add2(u64 a, u64 b) {
    u64 r; asm("add.rn.f32x2 %0, %1, %2;" : "=l"(r) : "l"(a), "l"(b)); return r;
}
__device__ __forceinline__ void unpack2(u64 v, float& lo, float& hi) {
    asm("mov.b64 {%0, %1}, %2;" : "=f"(lo), "=f"(hi) : "l"(v));
}
__device__ __forceinline__ void lds_v2u64(u64& a, u64& b, const void* p) {
    u64 g = __cvta_generic_to_shared(p);
    asm("ld.shared.v2.b64 {%0, %1}, [%2];" : "=l"(a), "=l"(b) : "l"(g));
}

__global__ __launch_bounds__(TPB, 3)
void chamfer_partial_kernel(const float* __restrict__ points,
                            const float* __restrict__ points_trans) {
    const int blk    = blockIdx.x;              // 0..2047
    const int s      = blk & (SPLITS - 1);
    const int isplit = (blk >> 6) & (ISPLITS - 1);
    const int b      = blk >> 8;

    const float* p1b = points       + b * 3 * NPTS;   // i side
    const float* p2b = points_trans + b * 3 * NPTS;   // j side

    // smem per j-pair: A = {-2x0,-2x1,-2y0,-2y1}, B = {-2z0,-2z1, n0, n1}
    __shared__ __align__(16) float sjA[JPAIRS * 4];
    __shared__ __align__(16) float sjB[JPAIRS * 4];
    __shared__ __align__(16) float2 colacc[8][JPAIRS];   // [warp][jp] (lo=j0, hi=j1)

    const int t = threadIdx.x;
    const int g = t >> 5;                        // warp id 0..7

    if (t < 16) {                                // 16 thr x 4 j = 64 = JCHUNK
        int j = s * JCHUNK + 4 * t;
        float4 X = *(const float4*)&p2b[j];
        float4 Y = *(const float4*)&p2b[NPTS + j];
        float4 Z = *(const float4*)&p2b[2 * NPTS + j];
        float4* A = (float4*)&sjA[8 * t];
        A[0] = make_float4(-2.f * X.x, -2.f * X.y, -2.f * Y.x, -2.f * Y.y);
        A[1] = make_float4(-2.f * X.z, -2.f * X.w, -2.f * Y.z, -2.f * Y.w);
        float4* Bv = (float4*)&sjB[8 * t];
        Bv[0] = make_float4(-2.f * Z.x, -2.f * Z.y,
                            X.x * X.x + Y.x * Y.x + Z.x * Z.x,
                            X.y * X.y + Y.y * Y.y + Z.y * Z.y);
        Bv[1] = make_float4(-2.f * Z.z, -2.f * Z.w,
                            X.z * X.z + Y.z * Y.z + Z.z * Z.z,
                            X.w * X.w + Y.w * Y.w + Z.w * Z.w);
    }
    colacc[g][t & 31] = make_float2(3.0e38f, 3.0e38f);   // init; iter-0 reader = same lane

    const int ib = isplit * (TPB * IPER) + 4 * t;
    float4 vx = *(const float4*)&p1b[ib];
    float4 vy = *(const float4*)&p1b[NPTS + ib];
    float4 vz = *(const float4*)&p1b[2 * NPTS + ib];

    float xs[IPER] = {vx.x, vx.y, vx.z, vx.w};
    float ys[IPER] = {vy.x, vy.y, vy.z, vy.w};
    float zs[IPER] = {vz.x, vz.y, vz.z, vz.w};

    u64 Xb[IPER], Yb[IPER], Zb[IPER], N1b[IPER];
#pragma unroll
    for (int k = 0; k < IPER; ++k) {
        float n1 = xs[k] * xs[k] + ys[k] * ys[k] + zs[k] * zs[k];
        N1b[k] = pack2(n1, n1);
        Xb[k] = pack2(xs[k], xs[k]);
        Yb[k] = pack2(ys[k], ys[k]);
        Zb[k] = pack2(zs[k], zs[k]);
    }

    float mnlo[IPER], mnhi[IPER];
#pragma unroll
    for (int k = 0; k < IPER; ++k) { mnlo[k] = 3.0e38f; mnhi[k] = 3.0e38f; }

    __syncthreads();

#pragma unroll 4
    for (int iter = 0; iter < JPAIRS; ++iter) {
        const int jp = (t + iter) & 31;          // rotation: unique (warp,jp) writer
        u64 xj, yj, zj, nj;
        lds_v2u64(xj, yj, &sjA[4 * jp]);
        lds_v2u64(zj, nj, &sjB[4 * jp]);

        u64 d0 = fma2(Zb[0], zj, add2(N1b[0], nj));
        u64 d1 = fma2(Zb[1], zj, add2(N1b[1], nj));
        u64 d2 = fma2(Zb[2], zj, add2(N1b[2], nj));
        u64 d3 = fma2(Zb[3], zj, add2(N1b[3], nj));
        d0 = fma2(Yb[0], yj, d0);
        d1 = fma2(Yb[1], yj, d1);
        d2 = fma2(Yb[2], yj, d2);
        d3 = fma2(Yb[3], yj, d3);
        d0 = fma2(Xb[0], xj, d0);
        d1 = fma2(Xb[1], xj, d1);
        d2 = fma2(Xb[2], xj, d2);
        d3 = fma2(Xb[3], xj, d3);

        float l0, h0, l1, h1, l2, h2, l3, h3;
        unpack2(d0, l0, h0); unpack2(d1, l1, h1);
        unpack2(d2, l2, h2); unpack2(d3, l3, h3);

        // row mins (full d: n1 already included)
        mnlo[0] = fminf(mnlo[0], l0); mnhi[0] = fminf(mnhi[0], h0);
        mnlo[1] = fminf(mnlo[1], l1); mnhi[1] = fminf(mnhi[1], h1);
        mnlo[2] = fminf(mnlo[2], l2); mnhi[2] = fminf(mnhi[2], h2);
        mnlo[3] = fminf(mnlo[3], l3); mnhi[3] = fminf(mnhi[3], h3);

        // col contribution: min over this thread's 4 i, accumulated into the slot
        float clo = fminf(fminf(l0, l1), fminf(l2, l3));
        float chi = fminf(fminf(h0, h1), fminf(h2, h3));
        float2 old = colacc[g][jp];              // written last iter by another lane
        colacc[g][jp] = make_float2(fminf(old.x, clo), fminf(old.y, chi));
        __syncwarp();                            // order cross-lane RAW for next iter
    }

    // row partial store (d already complete)
    {
        float* dst = g_row + ((size_t)(b * SPLITS + s)) * NPTS;
        float4 r;
        r.x = fminf(mnlo[0], mnhi[0]);
        r.y = fminf(mnlo[1], mnhi[1]);
        r.z = fminf(mnlo[2], mnhi[2]);
        r.w = fminf(mnlo[3], mnhi[3]);
        *(float4*)&dst[ib] = r;
    }

    __syncthreads();

    // col partial: min over the 8 warps' contributions, 64 j per block
    if (t < JCHUNK) {
        const int jp = t >> 1, lane = t & 1;
        float m = 3.0e38f;
#pragma unroll
        for (int w = 0; w < 8; ++w) {
            float2 c = colacc[w][jp];
            m = fminf(m, lane ? c.y : c.x);
        }
        g_col[((size_t)(b * ISPLITS + isplit)) * NPTS + s * JCHUNK + t] = m;
    }
}

__global__ __launch_bounds__(TPB)
void chamfer_reduce_kernel() {
    const int blk = blockIdx.x;
    const int t   = threadIdx.x;
    __shared__ float red[TPB];

    if (blk < 32) {
        // rows: b = blk>>2, i-chunk = blk&3 (1024 i each)
        const int b  = blk >> 2;
        const int ic = blk & 3;
        const float* base = g_row + (size_t)b * SPLITS * NPTS;
        const int i = ic * 1024 + 4 * t;

        float4 m = make_float4(3.0e38f, 3.0e38f, 3.0e38f, 3.0e38f);
#pragma unroll 16
        for (int s2 = 0; s2 < SPLITS; ++s2) {
            float4 v = *(const float4*)&base[s2 * NPTS + i];
            m.x = fminf(m.x, v.x); m.y = fminf(m.y, v.y);
            m.z = fminf(m.z, v.z); m.w = fminf(m.w, v.w);
        }
        red[t] = (m.x + m.y) + (m.z + m.w);
        __syncthreads();
        for (int off = TPB / 2; off >= 32; off >>= 1) {
            if (t < off) red[t] += red[t + off];
            __syncthreads();
        }
        if (t < 32) {
            float v = red[t];
#pragma unroll
            for (int off = 16; off > 0; off >>= 1)
                v += __shfl_xor_sync(0xFFFFFFFFu, v, off);
            if (t == 0) g_sums[b * 4 + ic] = v;
        }
    } else {
        // cols: b = blk-32; min over 4 isplits, sum over 4096 j
        const int b = blk - 32;
        const float* base = g_col + (size_t)b * ISPLITS * NPTS;
        float sum = 0.0f;
#pragma unroll
        for (int q = 0; q < 4; ++q) {
            const int j = q * 1024 + 4 * t;
            float4 m = make_float4(3.0e38f, 3.0e38f, 3.0e38f, 3.0e38f);
#pragma unroll
            for (int is = 0; is < ISPLITS; ++is) {
                float4 v = *(const float4*)&base[is * NPTS + j];
                m.x = fminf(m.x, v.x); m.y = fminf(m.y, v.y);
                m.z = fminf(m.z, v.z); m.w = fminf(m.w, v.w);
            }
            sum += (m.x + m.y) + (m.z + m.w);
        }
        red[t] = sum;
        __syncthreads();
        for (int off = TPB / 2; off >= 32; off >>= 1) {
            if (t < off) red[t] += red[t + off];
            __syncthreads();
        }
        if (t < 32) {
            float v = red[t];
#pragma unroll
            for (int off = 16; off > 0; off >>= 1)
                v += __shfl_xor_sync(0xFFFFFFFFu, v, off);
            if (t == 0) g_colsum[b] = v;
        }
    }
}

__global__ void mse_kernel(const float* __restrict__ pred, float* __restrict__ out) {
    int t = threadIdx.x;
    float v = 0.0f;
    if (t < 16) {
        const int b = t >> 1, c = t & 1;
        float s;
        if (c == 0) {
            s = (g_sums[b * 4 + 0] + g_sums[b * 4 + 1]) +
                (g_sums[b * 4 + 2] + g_sums[b * 4 + 3]);
        } else {
            s = g_colsum[b];
        }
        float cham = s * (1.0f / (float)NPTS);
        float d = pred[t] - cham;
        v = d * d;
    }
#pragma unroll
    for (int off = 16; off > 0; off >>= 1)
        v += __shfl_xor_sync(0xFFFFFFFFu, v, off);
    if (t == 0) out[0] = v * (1.0f / 16.0f);
}

extern "C" void kernel_launch(void* const* d_in, const int* in_sizes, int n_in,
                              void* d_out, int out_size) {
    const float* pred         = (const float*)d_in[0];   // [8,2]
    const float* points       = (const float*)d_in[1];   // [8,3,4096]
    const float* points_trans = (const float*)d_in[2];   // [8,3,4096]
    float* out = (float*)d_out;

    chamfer_partial_kernel<<<8 * ISPLITS * SPLITS, TPB>>>(points, points_trans);
    chamfer_reduce_kernel<<<40, TPB>>>();
    mse_kernel<<<1, 32>>>(pred, out);
}

// round 16
// speedup vs baseline: 1.1652x; 1.0706x over previous
#include <cuda_runtime.h>
#include <cuda_bf16.h>

// B=8, D=3, N=M=4096 fused chamfer + MSE — SHARED distance matrix.
// d(i,j) serves BOTH directions: d1 = row-min, d2 = col-min.
// d = fma2-chain( (n1_i + n2_j) - 2*dot ), f32x2 lanes carry a j-pair.
// Col-min: lane L owns the accumulator for jp=L; each iteration's
// contribution (for jp=(lane+iter)&31) is routed to its owner lane with one
// rotation shuffle -> zero smem traffic in the loop, no syncwarp.
// Kernel 1: 2048 blocks = b(8) x isplit(4) x jsplit(64), 256 thr, IPER=4.
// Kernel 2: 96 blocks: rows (64: b x 8 ichunks) + cols (32: b x 4 jchunks).
// Kernel 3: 1 warp: means + MSE.

#define NPTS    4096
#define SPLITS  64
#define JCHUNK  64
#define JPAIRS  32
#define ISPLITS 4
#define TPB     256
#define IPER    4            // ISPLITS*TPB*IPER = 4096 = NPTS (exact cover)

__device__ float g_row[8 * SPLITS * NPTS];     // 8 MB row partial mins
__device__ float g_col[8 * ISPLITS * NPTS];    // 512 KB col partial mins
__device__ float g_sums[8 * 8];                // row partial sums (b x ichunk)
__device__ float g_colsum[8 * 4];              // col partial sums (b x jchunk)

typedef unsigned long long u64;

__device__ __forceinline__ u64 pack2(float lo, float hi) {
    u64 r; asm("mov.b64 %0, {%1, %2};" : "=l"(r) : "f"(lo), "f"(hi)); return r;
}
__device__ __forceinline__ u64 fma2(u64 a, u64 b, u64 c) {
    u64 r; asm("fma.rn.f32x2 %0, %1, %2, %3;" : "=l"(r) : "l"(a), "l"(b), "l"(c)); return r;
}
__device__ __forceinline__ u64 add2(u64 a, u64 b) {
    u64 r; asm("add.rn.f32x2 %0, %1, %2;" : "=l"(r) : "l"(a), "l"(b)); return r;
}
__device__ __forceinline__ void unpack2(u64 v, float& lo, float& hi) {
    asm("mov.b64 {%0, %1}, %2;" : "=f"(lo), "=f"(hi) : "l"(v));
}
__device__ __forceinline__ void lds_v2u64(u64& a, u64& b, const void* p) {
    u64 g = __cvta_generic_to_shared(p);
    asm("ld.shared.v2.b64 {%0, %1}, [%2];" : "=l"(a), "=l"(b) : "l"(g));
}

__global__ __launch_bounds__(TPB, 3)
void chamfer_partial_kernel(const float* __restrict__ points,
                            const float* __restrict__ points_trans) {
    const int blk    = blockIdx.x;              // 0..2047
    const int s      = blk & (SPLITS - 1);
    const int isplit = (blk >> 6) & (ISPLITS - 1);
    const int b      = blk >> 8;

    const float* p1b = points       + b * 3 * NPTS;   // i side
    const float* p2b = points_trans + b * 3 * NPTS;   // j side

    __shared__ __align__(16) float sjA[JPAIRS * 4];
    __shared__ __align__(16) float sjB[JPAIRS * 4];
    __shared__ __align__(16) float2 colacc[8][JPAIRS];   // written once at end

    const int t    = threadIdx.x;
    const int g    = t >> 5;                     // warp 0..7
    const int lane = t & 31;

    if (t < 16) {                                // 16 thr x 4 j = 64 = JCHUNK
        int j = s * JCHUNK + 4 * t;
        float4 X = *(const float4*)&p2b[j];
        float4 Y = *(const float4*)&p2b[NPTS + j];
        float4 Z = *(const float4*)&p2b[2 * NPTS + j];
        float4* A = (float4*)&sjA[8 * t];
        A[0] = make_float4(-2.f * X.x, -2.f * X.y, -2.f * Y.x, -2.f * Y.y);
        A[1] = make_float4(-2.f * X.z, -2.f * X.w, -2.f * Y.z, -2.f * Y.w);
        float4* Bv = (float4*)&sjB[8 * t];
        Bv[0] = make_float4(-2.f * Z.x, -2.f * Z.y,
                            X.x * X.x + Y.x * Y.x + Z.x * Z.x,
                            X.y * X.y + Y.y * Y.y + Z.y * Z.y);
        Bv[1] = make_float4(-2.f * Z.z, -2.f * Z.w,
                            X.z * X.z + Y.z * Y.z + Z.z * Z.z,
                            X.w * X.w + Y.w * Y.w + Z.w * Z.w);
    }

    const int ib = isplit * (TPB * IPER) + 4 * t;
    float4 vx = *(const float4*)&p1b[ib];
    float4 vy = *(const float4*)&p1b[NPTS + ib];
    float4 vz = *(const float4*)&p1b[2 * NPTS + ib];

    float xs[IPER] = {vx.x, vx.y, vx.z, vx.w};
    float ys[IPER] = {vy.x, vy.y, vy.z, vy.w};
    float zs[IPER] = {vz.x, vz.y, vz.z, vz.w};

    u64 Xb[IPER], Yb[IPER], Zb[IPER], N1b[IPER];
#pragma unroll
    for (int k = 0; k < IPER; ++k) {
        float n1 = xs[k] * xs[k] + ys[k] * ys[k] + zs[k] * zs[k];
        N1b[k] = pack2(n1, n1);
        Xb[k] = pack2(xs[k], xs[k]);
        Yb[k] = pack2(ys[k], ys[k]);
        Zb[k] = pack2(zs[k], zs[k]);
    }

    float mnlo[IPER], mnhi[IPER];
#pragma unroll
    for (int k = 0; k < IPER; ++k) { mnlo[k] = 3.0e38f; mnhi[k] = 3.0e38f; }

    float cminlo = 3.0e38f, cminhi = 3.0e38f;    // owned jp = lane

    __syncthreads();

#pragma unroll 4
    for (int iter = 0; iter < JPAIRS; ++iter) {
        const int jp = (lane + iter) & 31;       // this lane's jp this iter
        u64 xj, yj, zj, nj;
        lds_v2u64(xj, yj, &sjA[4 * jp]);
        lds_v2u64(zj, nj, &sjB[4 * jp]);

        u64 d0 = fma2(Zb[0], zj, add2(N1b[0], nj));
        u64 d1 = fma2(Zb[1], zj, add2(N1b[1], nj));
        u64 d2 = fma2(Zb[2], zj, add2(N1b[2], nj));
        u64 d3 = fma2(Zb[3], zj, add2(N1b[3], nj));
        d0 = fma2(Yb[0], yj, d0);
        d1 = fma2(Yb[1], yj, d1);
        d2 = fma2(Yb[2], yj, d2);
        d3 = fma2(Yb[3], yj, d3);
        d0 = fma2(Xb[0], xj, d0);
        d1 = fma2(Xb[1], xj, d1);
        d2 = fma2(Xb[2], xj, d2);
        d3 = fma2(Xb[3], xj, d3);

        float l0, h0, l1, h1, l2, h2, l3, h3;
        unpack2(d0, l0, h0); unpack2(d1, l1, h1);
        unpack2(d2, l2, h2); unpack2(d3, l3, h3);

        // row mins
        mnlo[0] = fminf(mnlo[0], l0); mnhi[0] = fminf(mnhi[0], h0);
        mnlo[1] = fminf(mnlo[1], l1); mnhi[1] = fminf(mnhi[1], h1);
        mnlo[2] = fminf(mnlo[2], l2); mnhi[2] = fminf(mnhi[2], h2);
        mnlo[3] = fminf(mnlo[3], l3); mnhi[3] = fminf(mnhi[3], h3);

        // col contribution for jp (min over this thread's 4 i), routed to
        // owner lane jp via rotation shuffle: receiver r takes from lane
        // (r - iter) & 31, whose jp == r.
        float clo = fminf(fminf(l0, l1), fminf(l2, l3));
        float chi = fminf(fminf(h0, h1), fminf(h2, h3));
        int src = (lane - iter) & 31;
        float rlo = __shfl_sync(0xFFFFFFFFu, clo, src);
        float rhi = __shfl_sync(0xFFFFFFFFu, chi, src);
        cminlo = fminf(cminlo, rlo);
        cminhi = fminf(cminhi, rhi);
    }

    // row partial store
    {
        float* dst = g_row + ((size_t)(b * SPLITS + s)) * NPTS;
        float4 r;
        r.x = fminf(mnlo[0], mnhi[0]);
        r.y = fminf(mnlo[1], mnhi[1]);
        r.z = fminf(mnlo[2], mnhi[2]);
        r.w = fminf(mnlo[3], mnhi[3]);
        *(float4*)&dst[ib] = r;
    }

    colacc[g][lane] = make_float2(cminlo, cminhi);   // single STS per thread
    __syncthreads();

    // col partial: min over the 8 warps, 64 j per block
    if (t < JCHUNK) {
        const int jp = t >> 1, half = t & 1;
        float m = 3.0e38f;
#pragma unroll
        for (int w = 0; w < 8; ++w) {
            float2 c = colacc[w][jp];
            m = fminf(m, half ? c.y : c.x);
        }
        g_col[((size_t)(b * ISPLITS + isplit)) * NPTS + s * JCHUNK + t] = m;
    }
}

__global__ __launch_bounds__(TPB)
void chamfer_reduce_kernel() {
    const int blk = blockIdx.x;
    const int t   = threadIdx.x;
    __shared__ float red[TPB];

    float val = 0.0f;
    if (blk < 64) {
        // rows: b = blk>>3, ichunk = blk&7 (512 i each); t<128 active (float4)
        const int b  = blk >> 3;
        const int ic = blk & 7;
        if (t < 128) {
            const float* base = g_row + (size_t)b * SPLITS * NPTS;
            const int i = ic * 512 + 4 * t;
            float4 m = make_float4(3.0e38f, 3.0e38f, 3.0e38f, 3.0e38f);
#pragma unroll 16
            for (int s2 = 0; s2 < SPLITS; ++s2) {
                float4 v = *(const float4*)&base[s2 * NPTS + i];
                m.x = fminf(m.x, v.x); m.y = fminf(m.y, v.y);
                m.z = fminf(m.z, v.z); m.w = fminf(m.w, v.w);
            }
            val = (m.x + m.y) + (m.z + m.w);
        }
    } else {
        // cols: b = (blk-64)>>2, jchunk = (blk-64)&3 (1024 j each); all active
        const int b  = (blk - 64) >> 2;
        const int jc = (blk - 64) & 3;
        const float* base = g_col + (size_t)b * ISPLITS * NPTS;
        const int j = jc * 1024 + 4 * t;
        float4 m = make_float4(3.0e38f, 3.0e38f, 3.0e38f, 3.0e38f);
#pragma unroll
        for (int is = 0; is < ISPLITS; ++is) {
            float4 v = *(const float4*)&base[is * NPTS + j];
            m.x = fminf(m.x, v.x); m.y = fminf(m.y, v.y);
            m.z = fminf(m.z, v.z); m.w = fminf(m.w, v.w);
        }
        val = (m.x + m.y) + (m.z + m.w);
    }

    red[t] = val;
    __syncthreads();
    for (int off = TPB / 2; off >= 32; off >>= 1) {
        if (t < off) red[t] += red[t + off];
        __syncthreads();
    }
    if (t < 32) {
        float v = red[t];
#pragma unroll
        for (int off = 16; off > 0; off >>= 1)
            v += __shfl_xor_sync(0xFFFFFFFFu, v, off);
        if (t == 0) {
            if (blk < 64) g_sums[blk] = v;            // b*8 + ic
            else          g_colsum[blk - 64] = v;     // b*4 + jc
        }
    }
}

__global__ void mse_kernel(const float* __restrict__ pred, float* __restrict__ out) {
    int t = threadIdx.x;
    float v = 0.0f;
    if (t < 16) {
        const int b = t >> 1, c = t & 1;
        float s = 0.0f;
        if (c == 0) {
#pragma unroll
            for (int k = 0; k < 8; ++k) s += g_sums[b * 8 + k];
        } else {
#pragma unroll
            for (int k = 0; k < 4; ++k) s += g_colsum[b * 4 + k];
        }
        float cham = s * (1.0f / (float)NPTS);
        float d = pred[t] - cham;
        v = d * d;
    }
#pragma unroll
    for (int off = 16; off > 0; off >>= 1)
        v += __shfl_xor_sync(0xFFFFFFFFu, v, off);
    if (t == 0) out[0] = v * (1.0f / 16.0f);
}

extern "C" void kernel_launch(void* const* d_in, const int* in_sizes, int n_in,
                              void* d_out, int out_size) {
    const float* pred         = (const float*)d_in[0];   // [8,2]
    const float* points       = (const float*)d_in[1];   // [8,3,4096]
    const float* points_trans = (const float*)d_in[2];   // [8,3,4096]
    float* out = (float*)d_out;

    chamfer_partial_kernel<<<8 * ISPLITS * SPLITS, TPB>>>(points, points_trans);
    chamfer_reduce_kernel<<<96, TPB>>>();
    mse_kernel<<<1, 32>>>(pred, out);
}